// round 16
// baseline (speedup 1.0000x reference)
#include <cuda_runtime.h>
#include <cstddef>

#define NN   100000
#define EE   1600000
#define IND  128
#define HH   64
#define RR   4
#define GG   128
#define OUTD 10
#define MCP  1024  // padded concatenated width (960 used + 64 zero pad)
#define RN   (RR * NN)          // 400000 (r,dst) bins
#define SCAN_BS 1024
#define SCAN_NB ((RN + SCAN_BS - 1) / SCAN_BS)   // 391

// Column offsets inside C[N, MCP]
#define OFF_SKIPW 0
#define OFF_SBETA 64
#define OFF_SGAMM 128
#define OFF_HREL  192   // + r*64
#define OFF_FILM  448   // + r*128  (beta 0..63 | gamma 64..127)

// ---------------------------------------------------------------------------
// Scratch (static __device__ globals; no allocation anywhere)
// ---------------------------------------------------------------------------
__device__ float g_h0  [(size_t)NN * HH];
__device__ float g_h1  [(size_t)NN * HH];
__device__ float g_C   [(size_t)NN * MCP];
__device__ float g_Wcat[2][(size_t)HH * MCP];
__device__ float g_pool[GG * HH];
// CSR build (shared by both layers)
__device__ int   g_icnt  [RN];
__device__ int   g_off   [RN];
__device__ int   g_cursor[RN];
__device__ int   g_bsum  [SCAN_NB + 1];
__device__ int   g_ssrc  [EE];

// ---------------------------------------------------------------------------
// Helpers
// ---------------------------------------------------------------------------
__device__ __forceinline__ void redAddF4(float4* p, float4 v) {
    asm volatile("red.global.add.v4.f32 [%0], {%1, %2, %3, %4};"
                 :: "l"(p), "f"(v.x), "f"(v.y), "f"(v.z), "f"(v.w) : "memory");
}
__device__ __forceinline__ float2 unpackf2(unsigned long long u) {
    float2 f;
    asm("mov.b64 {%0, %1}, %2;" : "=f"(f.x), "=f"(f.y) : "l"(u));
    return f;
}
__device__ __forceinline__ unsigned long long fma2(unsigned long long a,
                                                   unsigned long long b,
                                                   unsigned long long c) {
    unsigned long long d;
    asm("fma.rn.f32x2 %0, %1, %2, %3;" : "=l"(d) : "l"(a), "l"(b), "l"(c));
    return d;
}

// ---------------------------------------------------------------------------
// Weight pack into [HH, MCP]; zero pad beyond 960.
// ---------------------------------------------------------------------------
__global__ void pack_weights_kernel(const float* __restrict__ Ws,
                                    const float* __restrict__ Fs,
                                    const float* __restrict__ Wr,
                                    const float* __restrict__ Fr,
                                    float* __restrict__ Wcat)
{
    int idx = blockIdx.x * blockDim.x + threadIdx.x;
    if (idx >= HH * MCP) return;
    int k = idx / MCP, m = idx % MCP;
    float v;
    if (m < 64)       v = Ws[k * 64 + m];
    else if (m < 192) v = Fs[k * 128 + (m - 64)];
    else if (m < 448) { int r = (m - 192) >> 6; int c = (m - 192) & 63;
                        v = Wr[((long)r * 64 + k) * 64 + c]; }
    else if (m < 960) { int r = (m - 448) >> 7; int c = (m - 448) & 127;
                        v = Fr[((long)r * 64 + k) * 128 + c]; }
    else              v = 0.f;
    Wcat[idx] = v;
}

// ---------------------------------------------------------------------------
// CSR build: histogram -> scan -> scatter
// ---------------------------------------------------------------------------
__global__ void hist_kernel(const int* __restrict__ dst,
                            const int* __restrict__ et,
                            int* __restrict__ icnt)
{
    int e = blockIdx.x * blockDim.x + threadIdx.x;
    if (e >= EE) return;
    atomicAdd(&icnt[et[e] * NN + dst[e]], 1);
}

__global__ __launch_bounds__(SCAN_BS)
void scan1_kernel(const int* __restrict__ in, int* __restrict__ out,
                  int* __restrict__ bsum, int n)
{
    __shared__ int sh[SCAN_BS];
    int tid = threadIdx.x;
    int i = blockIdx.x * SCAN_BS + tid;
    int v = (i < n) ? in[i] : 0;
    int x = v;
    sh[tid] = x;
    __syncthreads();
    for (int off = 1; off < SCAN_BS; off <<= 1) {
        int t = (tid >= off) ? sh[tid - off] : 0;
        __syncthreads();
        x += t;
        sh[tid] = x;
        __syncthreads();
    }
    if (i < n) out[i] = x - v;
    if (tid == SCAN_BS - 1) bsum[blockIdx.x] = x;
}

__global__ __launch_bounds__(SCAN_BS)
void scan2_kernel(int* __restrict__ bsum, int nb)
{
    __shared__ int sh[SCAN_BS];
    int tid = threadIdx.x;
    int v = (tid < nb) ? bsum[tid] : 0;
    int x = v;
    sh[tid] = x;
    __syncthreads();
    for (int off = 1; off < SCAN_BS; off <<= 1) {
        int t = (tid >= off) ? sh[tid - off] : 0;
        __syncthreads();
        x += t;
        sh[tid] = x;
        __syncthreads();
    }
    if (tid < nb) bsum[tid] = x - v;
}

__global__ void scan3b_kernel(int* __restrict__ out, const int* __restrict__ bsum, int n)
{
    int i = blockIdx.x * blockDim.x + threadIdx.x;
    if (i < n) out[i] += bsum[i / SCAN_BS];
}

__global__ void scatter_kernel(const int* __restrict__ src,
                               const int* __restrict__ dst,
                               const int* __restrict__ et,
                               const int* __restrict__ off,
                               int* __restrict__ cursor,
                               int* __restrict__ ssrc)
{
    int e = blockIdx.x * blockDim.x + threadIdx.x;
    if (e >= EE) return;
    int bin = et[e] * NN + dst[e];
    int pos = atomicAdd(&cursor[bin], 1);
    ssrc[off[bin] + pos] = src[e];
}

// ---------------------------------------------------------------------------
// Tiled fp32 GEMM with packed f32x2 FMA, W pre-duplicated in smem.
// C[N,M] = X[N,K] @ W[K,M] (+ bias). K % 32 == 0, M % TM == 0.
// Block tile 128(N) x TM(M), 256 threads, per-thread 8 rows (4 f32x2) x TCOL cols.
// ---------------------------------------------------------------------------
#define GT_N 128
#define GT_K 32

template<int TM>
__global__ __launch_bounds__(256)
void gemm_kernel(const float* __restrict__ X,
                 const float* __restrict__ W,
                 const float* __restrict__ bias,
                 float* __restrict__ C,
                 int N, int K, int M)
{
    constexpr int TCOL = TM / 16;                 // cols per thread (4 or 8)
    __shared__ __align__(16) float Xs[GT_K][GT_N + 2];   // transposed; stride 130 keeps 8B align
    __shared__ __align__(16) float Wd[GT_K][2 * TM];     // duplicated pairs (w,w)

    const int n0 = blockIdx.y * GT_N;
    const int m0 = blockIdx.x * TM;
    const int t  = threadIdx.x;
    const int tx = t & 15;     // col group
    const int ty = t >> 4;     // row group: 8 rows

    unsigned long long acc[4][TCOL];
    #pragma unroll
    for (int p = 0; p < 4; p++)
        #pragma unroll
        for (int c = 0; c < TCOL; c++) acc[p][c] = 0ULL;

    for (int k0 = 0; k0 < K; k0 += GT_K) {
        // X tile 128x32, coalesced global reads, transposed smem store
        #pragma unroll
        for (int idx = t; idx < GT_N * GT_K; idx += 256) {
            int r = idx >> 5, c = idx & 31;
            int n = n0 + r;
            Xs[c][r] = (n < N) ? X[(long)n * K + k0 + c] : 0.f;
        }
        // W tile 32xTM, stored duplicated: Wd[r][2c]=Wd[r][2c+1]=w
        #pragma unroll
        for (int idx = t; idx < GT_K * TM; idx += 256) {
            int r = idx / TM, c = idx % TM;
            float w = W[(long)(k0 + r) * M + m0 + c];
            *(float2*)&Wd[r][2 * c] = make_float2(w, w);
        }
        __syncthreads();

        #pragma unroll
        for (int kk = 0; kk < GT_K; kk++) {
            unsigned long long a[4];
            #pragma unroll
            for (int p = 0; p < 4; p++)
                a[p] = *(const unsigned long long*)&Xs[kk][ty * 8 + 2 * p];
            unsigned long long b[TCOL];
            const ulonglong2* bp = (const ulonglong2*)&Wd[kk][2 * tx * TCOL];
            #pragma unroll
            for (int c = 0; c < TCOL / 2; c++) {
                ulonglong2 bb = bp[c];
                b[2 * c] = bb.x;
                b[2 * c + 1] = bb.y;
            }
            #pragma unroll
            for (int p = 0; p < 4; p++)
                #pragma unroll
                for (int c = 0; c < TCOL; c++)
                    acc[p][c] = fma2(a[p], b[c], acc[p][c]);
        }
        __syncthreads();
    }

    float bv[TCOL];
    #pragma unroll
    for (int c = 0; c < TCOL; c++)
        bv[c] = bias ? bias[m0 + tx * TCOL + c] : 0.f;

    #pragma unroll
    for (int p = 0; p < 4; p++) {
        int n = n0 + ty * 8 + 2 * p;
        float lo[TCOL], hi[TCOL];
        #pragma unroll
        for (int c = 0; c < TCOL; c++) {
            float2 f = unpackf2(acc[p][c]);
            lo[c] = f.x + bv[c];
            hi[c] = f.y + bv[c];
        }
        if (n < N) {
            #pragma unroll
            for (int c = 0; c < TCOL; c += 4)
                *(float4*)&C[(long)n * M + m0 + tx * TCOL + c] =
                    make_float4(lo[c], lo[c + 1], lo[c + 2], lo[c + 3]);
        }
        if (n + 1 < N) {
            #pragma unroll
            for (int c = 0; c < TCOL; c += 4)
                *(float4*)&C[(long)(n + 1) * M + m0 + tx * TCOL + c] =
                    make_float4(hi[c], hi[c + 1], hi[c + 2], hi[c + 3]);
        }
    }
}

// ---------------------------------------------------------------------------
// Fused gather + finalize: one half-warp (16 lanes, float4) per NODE.
// For node d: v = relu(gamma_s*(h@Wskip) + beta_s)           [skip, from C]
//             for r in 0..3: v += mean_i relu(g[r,d]*h_rel[r,src_i] + b[r,d])
// mode 0: BN(eval)+ReLU -> out_nodes;  mode 1: red-add to pool[batch[d]].
// No intermediate sums array. CSR metadata for all 4 relations prefetched
// up-front (8 independent LDGs instead of serialized per-r dependent loads).
// src indices loaded cooperatively (16/chunk), broadcast via shfl with
// 16-lane mask + width=16 (each half-warp self-contained under divergence).
// ---------------------------------------------------------------------------
__global__ __launch_bounds__(256)
void gather_finalize_kernel(const int* __restrict__ ssrc,
                            const int* __restrict__ off,
                            const int* __restrict__ icnt,
                            const float* __restrict__ C,
                            const float* __restrict__ bn_g,
                            const float* __restrict__ bn_b,
                            float* __restrict__ out_nodes,
                            const int* __restrict__ batch,
                            float* __restrict__ pool,
                            int mode)
{
    int node   = (blockIdx.x * blockDim.x + threadIdx.x) >> 4;
    int lane16 = threadIdx.x & 15;                       // lane within half-warp
    unsigned hmask = 0xFFFFu << (threadIdx.x & 16);      // own half-warp mask
    if (node >= NN) return;

    // Prefetch CSR metadata for all relations (independent LDGs)
    int cArr[RR], bArr[RR];
    #pragma unroll
    for (int r = 0; r < RR; r++) {
        cArr[r] = icnt[r * NN + node];
        bArr[r] = off [r * NN + node];
    }

    const float* row = C + (long)node * MCP;

    // Skip connection: relu(gamma_s * w + beta_s)
    float4 w   = *(const float4*)(row + OFF_SKIPW + lane16 * 4);
    float4 bes = *(const float4*)(row + OFF_SBETA + lane16 * 4);
    float4 gas = *(const float4*)(row + OFF_SGAMM + lane16 * 4);
    float4 v;
    v.x = fmaxf(gas.x * w.x + bes.x, 0.f);
    v.y = fmaxf(gas.y * w.y + bes.y, 0.f);
    v.z = fmaxf(gas.z * w.z + bes.z, 0.f);
    v.w = fmaxf(gas.w * w.w + bes.w, 0.f);

    // Per-relation mean messages, accumulated directly
    #pragma unroll
    for (int r = 0; r < RR; r++) {
        int c = cArr[r];
        if (c <= 0) continue;
        const float4* f4 = (const float4*)(row + OFF_FILM + r * 128);
        float4 be = f4[lane16];
        float4 ga = f4[16 + lane16];
        float4 acc = make_float4(0.f, 0.f, 0.f, 0.f);
        int base = bArr[r];
        for (int i0 = 0; i0 < c; i0 += 16) {
            int nChunk = min(16, c - i0);
            int sv = (lane16 < nChunk) ? ssrc[base + i0 + lane16] : 0;
            #pragma unroll 4
            for (int j = 0; j < nChunk; j++) {
                int s = __shfl_sync(hmask, sv, j, 16);   // width=16: stays in half
                float4 h = *(const float4*)(C + (long)s * MCP + OFF_HREL + r * 64 + lane16 * 4);
                acc.x += fmaxf(ga.x * h.x + be.x, 0.f);
                acc.y += fmaxf(ga.y * h.y + be.y, 0.f);
                acc.z += fmaxf(ga.z * h.z + be.z, 0.f);
                acc.w += fmaxf(ga.w * h.w + be.w, 0.f);
            }
        }
        float inv = 1.0f / (float)c;
        v.x += acc.x * inv; v.y += acc.y * inv;
        v.z += acc.z * inv; v.w += acc.w * inv;
    }

    if (mode == 0) {
        int cb = lane16 * 4;
        float sc = rsqrtf(1.0f + 1e-5f);
        v.x = fmaxf(v.x * (bn_g[cb + 0] * sc) + bn_b[cb + 0], 0.f);
        v.y = fmaxf(v.y * (bn_g[cb + 1] * sc) + bn_b[cb + 1], 0.f);
        v.z = fmaxf(v.z * (bn_g[cb + 2] * sc) + bn_b[cb + 2], 0.f);
        v.w = fmaxf(v.w * (bn_g[cb + 3] * sc) + bn_b[cb + 3], 0.f);
        *(float4*)(out_nodes + (long)node * HH + lane16 * 4) = v;
    } else {
        int g = batch[node];
        redAddF4((float4*)(pool + (long)g * HH + lane16 * 4), v);
    }
}

// ---------------------------------------------------------------------------
// Head
// ---------------------------------------------------------------------------
__global__ __launch_bounds__(128)
void head_kernel(const float* __restrict__ pool,
                 const float* __restrict__ lin_W, const float* __restrict__ lin_b,
                 const float* __restrict__ clf_W, const float* __restrict__ clf_b,
                 float* __restrict__ out)
{
    __shared__ float sW[HH * HH];
    __shared__ float sC[HH * OUTD];
    __shared__ float sb[HH];
    __shared__ float scb[OUTD];
    int t = threadIdx.x;
    for (int i = t; i < HH * HH;   i += 128) sW[i] = lin_W[i];
    for (int i = t; i < HH * OUTD; i += 128) sC[i] = clf_W[i];
    if (t < HH)   sb[t]  = lin_b[t];
    if (t < OUTD) scb[t] = clf_b[t];
    __syncthreads();

    float p[HH];
    #pragma unroll
    for (int i = 0; i < HH; i++) p[i] = pool[t * HH + i];

    float hid[HH];
    #pragma unroll
    for (int j = 0; j < HH; j++) {
        float a = sb[j];
        #pragma unroll
        for (int i = 0; i < HH; i++) a += p[i] * sW[i * HH + j];
        hid[j] = fmaxf(a, 0.f);
    }
    #pragma unroll
    for (int o = 0; o < OUTD; o++) {
        float a = scb[o];
        #pragma unroll
        for (int j = 0; j < HH; j++) a += hid[j] * sC[j * OUTD + o];
        out[t * OUTD + o] = a;
    }
}

// ---------------------------------------------------------------------------
// Host orchestration.  Launch order keeps the DENSE GEMM (layer 0) as the
// 6th launch so ncu (-s 5 -c 1) profiles it.
// ---------------------------------------------------------------------------
static inline void* symAddr(const void* sym) {
    void* p = nullptr;
    cudaGetSymbolAddress(&p, sym);
    return p;
}

extern "C" void kernel_launch(void* const* d_in, const int* in_sizes, int n_in,
                              void* d_out, int out_size)
{
    const float* x        = (const float*)d_in[0];
    const int*   eidx     = (const int*)  d_in[1];
    const int*   etype    = (const int*)  d_in[2];
    const int*   batch    = (const int*)  d_in[3];
    const float* enc_W    = (const float*)d_in[4];
    const float* enc_b    = (const float*)d_in[5];
    const float* W_skip0  = (const float*)d_in[6];
    const float* F_skip0  = (const float*)d_in[7];
    const float* W_rel0   = (const float*)d_in[8];
    const float* F_rel0   = (const float*)d_in[9];
    const float* W_skip1  = (const float*)d_in[10];
    const float* F_skip1  = (const float*)d_in[11];
    const float* W_rel1   = (const float*)d_in[12];
    const float* F_rel1   = (const float*)d_in[13];
    const float* bn_g     = (const float*)d_in[14];
    const float* bn_b     = (const float*)d_in[15];
    const float* lin_W    = (const float*)d_in[16];
    const float* lin_b    = (const float*)d_in[17];
    const float* clf_W    = (const float*)d_in[18];
    const float* clf_b    = (const float*)d_in[19];
    float* out = (float*)d_out;

    const int* src = eidx;       // edge_index[0]
    const int* dst = eidx + EE;  // edge_index[1]

    float* h0     = (float*)symAddr(g_h0);
    float* h1     = (float*)symAddr(g_h1);
    float* C      = (float*)symAddr(g_C);
    float* Wc0    = (float*)symAddr(g_Wcat);
    float* Wc1    = Wc0 + (size_t)HH * MCP;
    float* pool   = (float*)symAddr(g_pool);
    int*   icnt   = (int*)symAddr(g_icnt);
    int*   off    = (int*)symAddr(g_off);
    int*   cursor = (int*)symAddr(g_cursor);
    int*   bsum   = (int*)symAddr(g_bsum);
    int*   ssrc   = (int*)symAddr(g_ssrc);

    const int NT = 256;
    const int nTilesN = (NN + GT_N - 1) / GT_N;   // 782

    // 1,2: pack weights
    pack_weights_kernel<<<(HH * MCP + NT - 1) / NT, NT>>>(W_skip0, F_skip0, W_rel0, F_rel0, Wc0);
    pack_weights_kernel<<<(HH * MCP + NT - 1) / NT, NT>>>(W_skip1, F_skip1, W_rel1, F_rel1, Wc1);
    // 3,4: memsets for CSR build
    cudaMemsetAsync(icnt,   0, (size_t)RN * sizeof(int));
    cudaMemsetAsync(cursor, 0, (size_t)RN * sizeof(int));
    // 5: encoder GEMM (h0 = x @ enc_W + enc_b)
    gemm_kernel<64><<<dim3(1, nTilesN), NT>>>(x, enc_W, enc_b, h0, NN, IND, HH);
    // 6: DENSE GEMM layer0 (profiled by ncu -s 5 -c 1)
    gemm_kernel<128><<<dim3(MCP / 128, nTilesN), NT>>>(h0, Wc0, nullptr, C, NN, HH, MCP);

    // CSR build over (r,dst) bins (shared by both layers)
    hist_kernel<<<(EE + NT - 1) / NT, NT>>>(dst, etype, icnt);
    scan1_kernel<<<SCAN_NB, SCAN_BS>>>(icnt, off, bsum, RN);
    scan2_kernel<<<1, SCAN_BS>>>(bsum, SCAN_NB);
    scan3b_kernel<<<SCAN_NB, SCAN_BS>>>(off, bsum, RN);
    scatter_kernel<<<(EE + NT - 1) / NT, NT>>>(src, dst, etype, off, cursor, ssrc);

    // layer 0: fused edge gather + skip + BN+ReLU -> h1
    gather_finalize_kernel<<<(unsigned)(((long)NN * 16 + NT - 1) / NT), NT>>>(
        ssrc, off, icnt, C, bn_g, bn_b, h1, nullptr, nullptr, 0);

    // layer 1
    gemm_kernel<128><<<dim3(MCP / 128, nTilesN), NT>>>(h1, Wc1, nullptr, C, NN, HH, MCP);
    cudaMemsetAsync(pool, 0, (size_t)GG * HH * sizeof(float));
    gather_finalize_kernel<<<(unsigned)(((long)NN * 16 + NT - 1) / NT), NT>>>(
        ssrc, off, icnt, C, nullptr, nullptr, nullptr, batch, pool, 1);

    // head
    head_kernel<<<1, 128>>>(pool, lin_W, lin_b, clf_W, clf_b, out);
}